// round 2
// baseline (speedup 1.0000x reference)
#include <cuda_runtime.h>

#define THREADS 256
#define RPB 16
#define LD_H 264
#define LD_W2 260

// smem layout (float offsets)
#define OFF_W0T 0
#define OFF_W2S 8192
#define OFF_B0  16512
#define OFF_B1  16768
#define OFF_B2  17024
#define OFF_Y   17056
#define OFF_K   17568
#define OFF_Z   20640
#define OFF_H0  21152
#define OFF_H1  25376
#define OFF_W1B 29600
#define SMEM_BYTES ((29600 + 16384) * 4)

__constant__ float c_A[6][5] = {
  {0.f,0.f,0.f,0.f,0.f},
  {0.161f,0.f,0.f,0.f,0.f},
  {-0.008480655492356989f,0.335480655492357f,0.f,0.f,0.f},
  {2.8971530571054935f,-6.359448489975075f,4.3622954328695815f,0.f,0.f},
  {5.325864828439257f,-11.748883564062828f,7.4955393428898365f,-0.09249506636175525f,0.f},
  {5.86145544294642f,-12.92096931784711f,8.159367898576159f,-0.071584973281401f,-0.028269050394068383f}};
__constant__ float c_B[6] = {
  0.09646076681806523f,0.01f,0.4798896504144996f,
  1.379008574103742f,-3.290069515436081f,2.324710524099774f};

__device__ float g_w1t[256 * 256]; // g_w1t[k*256+o] = W1[o*256+k]

__device__ __forceinline__ void cp16(float* dst, const float* src) {
  unsigned d = (unsigned)__cvta_generic_to_shared(dst);
  asm volatile("cp.async.ca.shared.global [%0], [%1], 16;" :: "r"(d), "l"(src));
}
__device__ __forceinline__ void cpcommit(){ asm volatile("cp.async.commit_group;"); }
template<int N> __device__ __forceinline__ void cpwait(){ asm volatile("cp.async.wait_group %0;"::"n"(N)); }

// FMA-only softplus (no MUFU)
__device__ __forceinline__ float softplusf(float x) {
  float xc = fminf(fmaxf(x, -87.0f), 16.0f);
  float t = xc * 1.4426950408889634f;
  float n = rintf(t);
  float f = t - n;
  float p = fmaf(f, 1.5404000e-4f, 1.3333558e-3f);
  p = fmaf(p, f, 9.6181291e-3f);
  p = fmaf(p, f, 5.5504109e-2f);
  p = fmaf(p, f, 2.4022651e-1f);
  p = fmaf(p, f, 6.9314718e-1f);
  p = fmaf(p, f, 1.0f);
  float e = __int_as_float(((int)n + 127) << 23) * p;
  float u = 1.0f + e;
  int iu = __float_as_int(u);
  int kk = (iu - 0x3f3504f3) >> 23;
  float m = __int_as_float(iu - (kk << 23));
  float w = m - 1.0f;
  float z = w * w;
  float pl = 7.0376836292e-2f;
  pl = fmaf(pl, w, -1.1514610310e-1f);
  pl = fmaf(pl, w, 1.1676998740e-1f);
  pl = fmaf(pl, w, -1.2420140846e-1f);
  pl = fmaf(pl, w, 1.4249322787e-1f);
  pl = fmaf(pl, w, -1.6668057665e-1f);
  pl = fmaf(pl, w, 2.0000714765e-1f);
  pl = fmaf(pl, w, -2.4999993993e-1f);
  pl = fmaf(pl, w, 3.3333331174e-1f);
  float r = pl * (z * w);
  r = fmaf(z, -0.5f, r) + w;
  r = fmaf((float)kk, 0.69314718055994531f, r);
  return (x > 15.0f) ? x : r;
}

__device__ __forceinline__ float f4get(const float4& v, int j) {
  return (j==0)?v.x:(j==1)?v.y:(j==2)?v.z:v.w;
}

__global__ void w1t_kernel(const float* __restrict__ W1) {
  __shared__ float tile[32][33];
  int k = blockIdx.x * 32 + threadIdx.x;
#pragma unroll
  for (int j = 0; j < 32; j += 8) {
    int o = blockIdx.y * 32 + threadIdx.y + j;
    tile[threadIdx.y + j][threadIdx.x] = W1[o * 256 + k];
  }
  __syncthreads();
  int o2 = blockIdx.y * 32 + threadIdx.x;
#pragma unroll
  for (int j = 0; j < 32; j += 8) {
    int k2 = blockIdx.x * 32 + threadIdx.y + j;
    g_w1t[k2 * 256 + o2] = tile[threadIdx.x][threadIdx.y + j];
  }
}

__global__ void __launch_bounds__(THREADS, 1)
ode_kernel(const float* __restrict__ ts, const float* __restrict__ y0,
           const float* __restrict__ W0, const float* __restrict__ b0,
           const float* __restrict__ b1, const float* __restrict__ W2,
           const float* __restrict__ b2, float* __restrict__ out, int T, int B) {
  extern __shared__ float sm[];
  float *w0t=sm+OFF_W0T, *w2s=sm+OFF_W2S, *b0s=sm+OFF_B0, *b1s=sm+OFF_B1,
        *b2s=sm+OFF_B2, *ysm=sm+OFF_Y, *ksm=sm+OFF_K, *zb=sm+OFF_Z,
        *h0=sm+OFF_H0, *h1=sm+OFF_H1, *w1b=sm+OFF_W1B;
  const int tid = threadIdx.x;
  const int rbase = blockIdx.x * RPB;

  for (int idx = tid; idx < 256*32; idx += THREADS) {
    int o = idx >> 5, k = idx & 31;
    w0t[k*256 + o] = W0[idx];
  }
  for (int idx = tid; idx < 32*256; idx += THREADS) {
    int d = idx >> 8, k = idx & 255;
    w2s[d*LD_W2 + k] = W2[idx];
  }
  for (int i = tid; i < 256; i += THREADS) { b0s[i]=b0[i]; b1s[i]=b1[i]; }
  if (tid < 32) b2s[tid] = b2[tid];
  for (int idx = tid; idx < RPB*32; idx += THREADS) {
    float v = y0[rbase*32 + idx];
    ysm[idx] = v;
    out[rbase*32 + idx] = v;
  }
  __syncthreads();

  const int cg = tid & 63, rg = tid >> 6;
  const int c0 = cg*4, r0 = rg*4;
  const int d2 = tid & 31, rr = (tid >> 5) * 2;

  for (int s = 0; s < T-1; ++s) {
    const float h = (ts[s+1] - ts[s]) * 0.5f;  // NSUB=2
    for (int sub = 0; sub < 2; ++sub) {
      for (int st = 0; st < 6; ++st) {
        // z = y + h * sum A[st][j] k_j
#pragma unroll
        for (int q = 0; q < 2; ++q) {
          int idx = q*THREADS + tid;
          float acc = ysm[idx];
          for (int j = 0; j < st; ++j)
            acc = fmaf(h * c_A[st][j], ksm[j*512 + idx], acc);
          zb[idx] = acc;
        }
        __syncthreads();

        // prefetch W1 tile 0
#pragma unroll
        for (int q = 0; q < 8; ++q) {
          int e = (q*THREADS + tid) * 4;
          cp16(w1b + e, g_w1t + e);
        }
        cpcommit();

        // layer 0: h0 = softplus(z @ W0^T + b0)
        float a0[4][4];
#pragma unroll
        for (int i=0;i<4;i++)
#pragma unroll
          for (int j=0;j<4;j++) a0[i][j]=0.f;
#pragma unroll
        for (int kk = 0; kk < 32; kk += 4) {
          float4 av[4], wv[4];
#pragma unroll
          for (int i=0;i<4;i++) av[i] = *(const float4*)(zb + (r0+i)*32 + kk);
#pragma unroll
          for (int t=0;t<4;t++) wv[t] = *(const float4*)(w0t + (kk+t)*256 + c0);
#pragma unroll
          for (int i=0;i<4;i++)
#pragma unroll
            for (int t=0;t<4;t++) {
              float aval = f4get(av[i], t);
#pragma unroll
              for (int j=0;j<4;j++) a0[i][j] = fmaf(aval, f4get(wv[t],j), a0[i][j]);
            }
        }
#pragma unroll
        for (int i=0;i<4;i++) {
          float4 o4;
          o4.x = softplusf(a0[i][0] + b0s[c0+0]);
          o4.y = softplusf(a0[i][1] + b0s[c0+1]);
          o4.z = softplusf(a0[i][2] + b0s[c0+2]);
          o4.w = softplusf(a0[i][3] + b0s[c0+3]);
          *(float4*)(h0 + (r0+i)*LD_H + c0) = o4;
        }
        __syncthreads();

        // layer 1: h1 = softplus(h0 @ W1^T + b1), W1 streamed 8x32 tiles
        float a1[4][4];
#pragma unroll
        for (int i=0;i<4;i++)
#pragma unroll
          for (int j=0;j<4;j++) a1[i][j]=0.f;
        for (int kt = 0; kt < 8; ++kt) {
          if (kt < 7) {
            const float* src = g_w1t + (kt+1)*8192;
            float* dst = w1b + ((kt+1)&1)*8192;
#pragma unroll
            for (int q = 0; q < 8; ++q) {
              int e = (q*THREADS + tid) * 4;
              cp16(dst + e, src + e);
            }
            cpcommit();
            cpwait<1>();
          } else {
            cpwait<0>();
          }
          __syncthreads();
          const float* wb = w1b + (kt&1)*8192;
          const int kb = kt*32;
#pragma unroll
          for (int kk = 0; kk < 32; kk += 4) {
            float4 av[4], wv[4];
#pragma unroll
            for (int i=0;i<4;i++) av[i] = *(const float4*)(h0 + (r0+i)*LD_H + kb + kk);
#pragma unroll
            for (int t=0;t<4;t++) wv[t] = *(const float4*)(wb + (kk+t)*256 + c0);
#pragma unroll
            for (int i=0;i<4;i++)
#pragma unroll
              for (int t=0;t<4;t++) {
                float aval = f4get(av[i], t);
#pragma unroll
                for (int j=0;j<4;j++) a1[i][j] = fmaf(aval, f4get(wv[t],j), a1[i][j]);
              }
          }
          __syncthreads();
        }
#pragma unroll
        for (int i=0;i<4;i++) {
          float4 o4;
          o4.x = softplusf(a1[i][0] + b1s[c0+0]);
          o4.y = softplusf(a1[i][1] + b1s[c0+1]);
          o4.z = softplusf(a1[i][2] + b1s[c0+2]);
          o4.w = softplusf(a1[i][3] + b1s[c0+3]);
          *(float4*)(h1 + (r0+i)*LD_H + c0) = o4;
        }
        __syncthreads();

        // layer 2: k_st = h1 @ W2^T + b2
        float s2a = 0.f, s2b = 0.f;
#pragma unroll 8
        for (int kk = 0; kk < 256; kk += 4) {
          float4 wv = *(const float4*)(w2s + d2*LD_W2 + kk);
          float4 ua = *(const float4*)(h1 + rr*LD_H + kk);
          float4 ub = *(const float4*)(h1 + (rr+1)*LD_H + kk);
          s2a = fmaf(ua.x, wv.x, s2a); s2a = fmaf(ua.y, wv.y, s2a);
          s2a = fmaf(ua.z, wv.z, s2a); s2a = fmaf(ua.w, wv.w, s2a);
          s2b = fmaf(ub.x, wv.x, s2b); s2b = fmaf(ub.y, wv.y, s2b);
          s2b = fmaf(ub.z, wv.z, s2b); s2b = fmaf(ub.w, wv.w, s2b);
        }
        ksm[st*512 + rr*32 + d2]     = s2a + b2s[d2];
        ksm[st*512 + (rr+1)*32 + d2] = s2b + b2s[d2];
        __syncthreads();
      } // stages

#pragma unroll
      for (int q = 0; q < 2; ++q) {
        int idx = q*THREADS + tid;
        float acc = ysm[idx];
#pragma unroll
        for (int j = 0; j < 6; ++j)
          acc = fmaf(h * c_B[j], ksm[j*512 + idx], acc);
        ysm[idx] = acc;
        if (sub == 1)
          out[(size_t)(s+1)*B*32 + rbase*32 + idx] = acc;
      }
      __syncthreads();
    } // sub
  } // intervals
}

extern "C" void kernel_launch(void* const* d_in, const int* in_sizes, int n_in,
                              void* d_out, int out_size) {
  const float* ts = (const float*)d_in[0];
  const float* y0 = (const float*)d_in[1];
  const float* W0 = (const float*)d_in[2];
  const float* b0 = (const float*)d_in[3];
  const float* W1 = (const float*)d_in[4];
  const float* b1 = (const float*)d_in[5];
  const float* W2 = (const float*)d_in[6];
  const float* b2 = (const float*)d_in[7];
  float* out = (float*)d_out;
  int T = in_sizes[0];
  int B = in_sizes[1] / 32;

  w1t_kernel<<<dim3(8, 8), dim3(32, 8)>>>(W1);

  static int smem_set = 0;
  if (!smem_set) {
    cudaFuncSetAttribute(ode_kernel, cudaFuncAttributeMaxDynamicSharedMemorySize, SMEM_BYTES);
    smem_set = 1;
  }
  ode_kernel<<<B / RPB, THREADS, SMEM_BYTES>>>(ts, y0, W0, b0, b1, W2, b2, out, T, B);
}

// round 3
// speedup vs baseline: 1.0701x; 1.0701x over previous
#include <cuda_runtime.h>

#define THREADS 256
#define RPB 16
#define LD_H 264
#define LD_W2 260

// smem layout (float offsets)
#define OFF_W0T 0
#define OFF_W2S 8192
#define OFF_B0  16512
#define OFF_B1  16768
#define OFF_B2  17024
#define OFF_Y   17056
#define OFF_K   17568
#define OFF_Z   20640
#define OFF_H0  21152
#define OFF_H1  25376
#define OFF_W1B 29600
#define SMEM_BYTES ((29600 + 3 * 8192) * 4)

typedef unsigned long long u64;

__constant__ float c_A[6][5] = {
  {0.f,0.f,0.f,0.f,0.f},
  {0.161f,0.f,0.f,0.f,0.f},
  {-0.008480655492356989f,0.335480655492357f,0.f,0.f,0.f},
  {2.8971530571054935f,-6.359448489975075f,4.3622954328695815f,0.f,0.f},
  {5.325864828439257f,-11.748883564062828f,7.4955393428898365f,-0.09249506636175525f,0.f},
  {5.86145544294642f,-12.92096931784711f,8.159367898576159f,-0.071584973281401f,-0.028269050394068383f}};
__constant__ float c_B[6] = {
  0.09646076681806523f,0.01f,0.4798896504144996f,
  1.379008574103742f,-3.290069515436081f,2.324710524099774f};

__device__ float g_w1t[256 * 256]; // g_w1t[k*256+o] = W1[o*256+k]

__device__ __forceinline__ void cp16(float* dst, const float* src) {
  unsigned d = (unsigned)__cvta_generic_to_shared(dst);
  asm volatile("cp.async.ca.shared.global [%0], [%1], 16;" :: "r"(d), "l"(src));
}
__device__ __forceinline__ void cpcommit(){ asm volatile("cp.async.commit_group;"); }
template<int N> __device__ __forceinline__ void cpwait(){ asm volatile("cp.async.wait_group %0;"::"n"(N)); }

// packed f32x2 helpers (Blackwell FFMA2)
__device__ __forceinline__ u64 dup2(float a) {
  u64 r; asm("mov.b64 %0, {%1, %1};" : "=l"(r) : "f"(a)); return r;
}
__device__ __forceinline__ float2 unpk(u64 v) {
  float2 r; asm("mov.b64 {%0, %1}, %2;" : "=f"(r.x), "=f"(r.y) : "l"(v)); return r;
}
__device__ __forceinline__ void ffma2(u64& acc, u64 a, u64 b) {
  asm("fma.rn.f32x2 %0, %1, %2, %0;" : "+l"(acc) : "l"(a), "l"(b));
}

// MUFU softplus: log(1+exp(x)) via ex2/lg2.approx
__device__ __forceinline__ float softplusf(float x) {
  float e, l;
  asm("ex2.approx.f32 %0, %1;" : "=f"(e) : "f"(x * 1.4426950408889634f));
  asm("lg2.approx.f32 %0, %1;" : "=f"(l) : "f"(1.0f + e));
  float r = l * 0.69314718055994531f;
  return (x > 15.0f) ? x : r;
}

__device__ __forceinline__ float f4get(const float4& v, int j) {
  return (j==0)?v.x:(j==1)?v.y:(j==2)?v.z:v.w;
}

__global__ void w1t_kernel(const float* __restrict__ W1) {
  __shared__ float tile[32][33];
  int k = blockIdx.x * 32 + threadIdx.x;
#pragma unroll
  for (int j = 0; j < 32; j += 8) {
    int o = blockIdx.y * 32 + threadIdx.y + j;
    tile[threadIdx.y + j][threadIdx.x] = W1[o * 256 + k];
  }
  __syncthreads();
  int o2 = blockIdx.y * 32 + threadIdx.x;
#pragma unroll
  for (int j = 0; j < 32; j += 8) {
    int k2 = blockIdx.x * 32 + threadIdx.y + j;
    g_w1t[k2 * 256 + o2] = tile[threadIdx.x][threadIdx.y + j];
  }
}

__global__ void __launch_bounds__(THREADS, 1)
ode_kernel(const float* __restrict__ ts, const float* __restrict__ y0,
           const float* __restrict__ W0, const float* __restrict__ b0,
           const float* __restrict__ b1, const float* __restrict__ W2,
           const float* __restrict__ b2, float* __restrict__ out, int T, int B) {
  extern __shared__ float sm[];
  float *w0t=sm+OFF_W0T, *w2s=sm+OFF_W2S, *b0s=sm+OFF_B0, *b1s=sm+OFF_B1,
        *b2s=sm+OFF_B2, *ysm=sm+OFF_Y, *ksm=sm+OFF_K, *zb=sm+OFF_Z,
        *h0=sm+OFF_H0, *h1=sm+OFF_H1, *w1b=sm+OFF_W1B;
  const int tid = threadIdx.x;
  const int rbase = blockIdx.x * RPB;

  for (int idx = tid; idx < 256*32; idx += THREADS) {
    int o = idx >> 5, k = idx & 31;
    w0t[k*256 + o] = W0[idx];
  }
  for (int idx = tid; idx < 32*256; idx += THREADS) {
    int d = idx >> 8, k = idx & 255;
    w2s[d*LD_W2 + k] = W2[idx];
  }
  for (int i = tid; i < 256; i += THREADS) { b0s[i]=b0[i]; b1s[i]=b1[i]; }
  if (tid < 32) b2s[tid] = b2[tid];
  for (int idx = tid; idx < RPB*32; idx += THREADS) {
    float v = y0[rbase*32 + idx];
    ysm[idx] = v;
    out[rbase*32 + idx] = v;
  }
  __syncthreads();

  const int cg = tid & 63, rg = tid >> 6;
  const int c0 = cg*4, r0 = rg*4;
  const int d2 = tid & 31, rr = (tid >> 5) * 2;

  for (int s = 0; s < T-1; ++s) {
    const float h = (ts[s+1] - ts[s]) * 0.5f;  // NSUB=2
    for (int sub = 0; sub < 2; ++sub) {
      for (int st = 0; st < 6; ++st) {
        // prefetch W1 tiles 0,1 (buffers free: all prior reads fenced by stage-end syncs)
#pragma unroll
        for (int q = 0; q < 8; ++q) {
          int e = (q*THREADS + tid) * 4;
          cp16(w1b + e, g_w1t + e);
        }
        cpcommit();
#pragma unroll
        for (int q = 0; q < 8; ++q) {
          int e = (q*THREADS + tid) * 4;
          cp16(w1b + 8192 + e, g_w1t + 8192 + e);
        }
        cpcommit();

        // z = y + h * sum A[st][j] k_j   (packed: 1 pair/thread)
        {
          u64 acc = *(const u64*)(ysm + tid*2);
          for (int j = 0; j < st; ++j)
            ffma2(acc, dup2(h * c_A[st][j]), *(const u64*)(ksm + j*512 + tid*2));
          *(u64*)(zb + tid*2) = acc;
        }
        __syncthreads();

        // layer 0: h0 = softplus(z @ W0^T + b0), K=32, f32x2 col-packed
        u64 a0[4][2];
        {
          u64 bp0 = *(const u64*)(b0s + c0);
          u64 bp1 = *(const u64*)(b0s + c0 + 2);
#pragma unroll
          for (int i=0;i<4;i++) { a0[i][0]=bp0; a0[i][1]=bp1; }
        }
#pragma unroll
        for (int kk = 0; kk < 32; kk += 4) {
          float4 av[4]; ulonglong2 wv[4];
#pragma unroll
          for (int i=0;i<4;i++) av[i] = *(const float4*)(zb + (r0+i)*32 + kk);
#pragma unroll
          for (int t=0;t<4;t++) wv[t] = *(const ulonglong2*)(w0t + (kk+t)*256 + c0);
#pragma unroll
          for (int t=0;t<4;t++)
#pragma unroll
            for (int i=0;i<4;i++) {
              u64 ad = dup2(f4get(av[i], t));
              ffma2(a0[i][0], ad, wv[t].x);
              ffma2(a0[i][1], ad, wv[t].y);
            }
        }
#pragma unroll
        for (int i=0;i<4;i++) {
          float2 u0 = unpk(a0[i][0]), u1 = unpk(a0[i][1]);
          float4 o4;
          o4.x = softplusf(u0.x); o4.y = softplusf(u0.y);
          o4.z = softplusf(u1.x); o4.w = softplusf(u1.y);
          *(float4*)(h0 + (r0+i)*LD_H + c0) = o4;
        }

        // layer 1: h1 = softplus(h0 @ W1^T + b1), K=256, triple-buffered stream
        u64 a1[4][2];
        {
          u64 bp0 = *(const u64*)(b1s + c0);
          u64 bp1 = *(const u64*)(b1s + c0 + 2);
#pragma unroll
          for (int i=0;i<4;i++) { a1[i][0]=bp0; a1[i][1]=bp1; }
        }
        for (int kt = 0; kt < 8; ++kt) {
          if (kt < 7) cpwait<1>(); else cpwait<0>();
          __syncthreads();  // tile kt landed for all; also fences h0 on kt==0
          if (kt < 6) {
            const float* src = g_w1t + (kt+2)*8192;
            float* dst = w1b + ((kt+2)%3)*8192;
#pragma unroll
            for (int q = 0; q < 8; ++q) {
              int e = (q*THREADS + tid) * 4;
              cp16(dst + e, src + e);
            }
            cpcommit();
          }
          const float* wb = w1b + (kt%3)*8192;
          const int kb = kt*32;
#pragma unroll
          for (int kk = 0; kk < 32; kk += 4) {
            float4 av[4]; ulonglong2 wv[4];
#pragma unroll
            for (int i=0;i<4;i++) av[i] = *(const float4*)(h0 + (r0+i)*LD_H + kb + kk);
#pragma unroll
            for (int t=0;t<4;t++) wv[t] = *(const ulonglong2*)(wb + (kk+t)*256 + c0);
#pragma unroll
            for (int t=0;t<4;t++)
#pragma unroll
              for (int i=0;i<4;i++) {
                u64 ad = dup2(f4get(av[i], t));
                ffma2(a1[i][0], ad, wv[t].x);
                ffma2(a1[i][1], ad, wv[t].y);
              }
          }
        }
#pragma unroll
        for (int i=0;i<4;i++) {
          float2 u0 = unpk(a1[i][0]), u1 = unpk(a1[i][1]);
          float4 o4;
          o4.x = softplusf(u0.x); o4.y = softplusf(u0.y);
          o4.z = softplusf(u1.x); o4.w = softplusf(u1.y);
          *(float4*)(h1 + (r0+i)*LD_H + c0) = o4;
        }
        __syncthreads();

        // layer 2: k_st = h1 @ W2^T + b2, K=256, f32x2 k-packed (no dups)
        u64 sa = 0ULL, sb = 0ULL;
#pragma unroll 8
        for (int kk = 0; kk < 256; kk += 4) {
          ulonglong2 wv = *(const ulonglong2*)(w2s + d2*LD_W2 + kk);
          ulonglong2 ua = *(const ulonglong2*)(h1 + rr*LD_H + kk);
          ulonglong2 ub = *(const ulonglong2*)(h1 + (rr+1)*LD_H + kk);
          ffma2(sa, ua.x, wv.x); ffma2(sa, ua.y, wv.y);
          ffma2(sb, ub.x, wv.x); ffma2(sb, ub.y, wv.y);
        }
        {
          float2 fa = unpk(sa), fb = unpk(sb);
          ksm[st*512 + rr*32 + d2]     = fa.x + fa.y + b2s[d2];
          ksm[st*512 + (rr+1)*32 + d2] = fb.x + fb.y + b2s[d2];
        }
        __syncthreads();
      } // stages

      // y += h * (B . k), packed; save at end of interval
      {
        u64 acc = *(const u64*)(ysm + tid*2);
#pragma unroll
        for (int j = 0; j < 6; ++j)
          ffma2(acc, dup2(h * c_B[j]), *(const u64*)(ksm + j*512 + tid*2));
        *(u64*)(ysm + tid*2) = acc;
        if (sub == 1)
          *(u64*)(out + (size_t)(s+1)*B*32 + rbase*32 + tid*2) = acc;
      }
      __syncthreads();
    } // sub
  } // intervals
}

extern "C" void kernel_launch(void* const* d_in, const int* in_sizes, int n_in,
                              void* d_out, int out_size) {
  const float* ts = (const float*)d_in[0];
  const float* y0 = (const float*)d_in[1];
  const float* W0 = (const float*)d_in[2];
  const float* b0 = (const float*)d_in[3];
  const float* W1 = (const float*)d_in[4];
  const float* b1 = (const float*)d_in[5];
  const float* W2 = (const float*)d_in[6];
  const float* b2 = (const float*)d_in[7];
  float* out = (float*)d_out;
  int T = in_sizes[0];
  int B = in_sizes[1] / 32;

  w1t_kernel<<<dim3(8, 8), dim3(32, 8)>>>(W1);

  static int smem_set = 0;
  if (!smem_set) {
    cudaFuncSetAttribute(ode_kernel, cudaFuncAttributeMaxDynamicSharedMemorySize, SMEM_BYTES);
    smem_set = 1;
  }
  ode_kernel<<<B / RPB, THREADS, SMEM_BYTES>>>(ts, y0, W0, b0, b1, W2, b2, out, T, B);
}